// round 3
// baseline (speedup 1.0000x reference)
#include <cuda_runtime.h>

// Spline1DInterpolant, compact-support closed form.
// s = (x-a)*n/(b-a); ib = floor(s); f = s - ib in [0,1); g = 1-f.
// y = c[ib]*g^3 + c[ib+1]*(4-6f^2+3f^3) + c[ib+2]*(4-6g^2+3g^3) + c[ib+3]*f^3
// Indices clamped to [0, C-1]; any clamped term has exact weight 0
// (t >= 2 there), so clamping never changes the value.
//
// Kernel is launch-overhead bound (~5.3us floor, DRAM 0.2%, all pipes <2%):
// this is the minimal-chain single-launch form.

__global__ __launch_bounds__(256, 1)
void spline1d_kernel(const float* __restrict__ x,
                     const float* __restrict__ a,
                     const float* __restrict__ b,
                     const float* __restrict__ n,
                     const float* __restrict__ c,
                     float* __restrict__ out,
                     int B, int C) {
    int tid = blockIdx.x * blockDim.x + threadIdx.x;
    if (tid >= B) return;

    float av = a[0];
    float inv_h = n[0] / (b[0] - av);
    float s = (x[tid] - av) * inv_h;        // s in [0, n]

    int ib = __float2int_rd(s);             // floor; s >= 0
    float f = s - (float)ib;                // [0,1)
    float g = 1.0f - f;

    float f2 = f * f, f3 = f2 * f;
    float g2 = g * g, g3 = g2 * g;

    float w0 = g3;
    float w1 = fmaf(3.0f, f3, fmaf(-6.0f, f2, 4.0f));
    float w2 = fmaf(3.0f, g3, fmaf(-6.0f, g2, 4.0f));
    float w3 = f3;

    int cm = C - 1;
    int i0 = min(max(ib,     0), cm);
    int i1 = min(max(ib + 1, 0), cm);
    int i2 = min(max(ib + 2, 0), cm);
    int i3 = min(max(ib + 3, 0), cm);

    float acc = c[i0] * w0;
    acc = fmaf(c[i1], w1, acc);
    acc = fmaf(c[i2], w2, acc);
    acc = fmaf(c[i3], w3, acc);
    out[tid] = acc;
}

extern "C" void kernel_launch(void* const* d_in, const int* in_sizes, int n_in,
                              void* d_out, int out_size) {
    const float* x = (const float*)d_in[0];
    const float* a = (const float*)d_in[1];
    const float* b = (const float*)d_in[2];
    const float* n = (const float*)d_in[3];
    const float* c = (const float*)d_in[4];
    float* out = (float*)d_out;

    int B = in_sizes[0];      // 16384
    int C = in_sizes[4];      // 4096

    int threads = 256;
    int blocks = (B + threads - 1) / threads;   // 64
    spline1d_kernel<<<blocks, threads>>>(x, a, b, n, c, out, B, C);
}